// round 1
// baseline (speedup 1.0000x reference)
#include <cuda_runtime.h>
#include <math.h>

#define N_NODES 200000
#define D 64
#define H 128
#define TILE 128
#define TPB_A 512

// Scratch (device globals; no allocation allowed)
__device__ float g_agg1[(size_t)N_NODES * D];
__device__ float g_agg2[(size_t)N_NODES * D];
__device__ float g_cnt1[N_NODES];
__device__ float g_cnt2[N_NODES];
__device__ float g_z[(size_t)3 * N_NODES * D];   // planes: 0=ident, 1=e1, 2=e2
__device__ float g_wpart[3];

// ---------------------------------------------------------------------------
__global__ void k_zero(int n) {
    int i = blockIdx.x * blockDim.x + threadIdx.x;
    int tot4 = n * (D / 4);
    if (i < tot4) {
        ((float4*)g_agg1)[i] = make_float4(0.f, 0.f, 0.f, 0.f);
        ((float4*)g_agg2)[i] = make_float4(0.f, 0.f, 0.f, 0.f);
    }
    if (i < n) { g_cnt1[i] = 0.f; g_cnt2[i] = 0.f; }
    if (i < 3) g_wpart[i] = 0.f;
}

// ---------------------------------------------------------------------------
// One thread handles (edge, 16B-chunk). 16 chunks cover the 64-float row.
// Degree count is folded in at chunk 0. The 1/deg weight is applied later
// (it depends only on dst, so it commutes with the segment sum).
__global__ void k_scatter(const float* __restrict__ h,
                          const int* __restrict__ s1, const int* __restrict__ d1,
                          const int* __restrict__ s2, const int* __restrict__ d2,
                          int E) {
    int t = blockIdx.x * blockDim.x + threadIdx.x;
    int e = t >> 4;
    int c = t & 15;
    if (e >= 2 * E) return;
    const int* sp; const int* dp; float* agg; float* cnt;
    if (e < E) { sp = s1; dp = d1; agg = g_agg1; cnt = g_cnt1; }
    else       { e -= E; sp = s2; dp = d2; agg = g_agg2; cnt = g_cnt2; }
    int s = sp[e], d = dp[e];
    float4 v = ((const float4*)h)[(size_t)s * 16 + c];
    float* p = agg + (size_t)d * 64 + c * 4;
    asm volatile("red.global.add.v4.f32 [%0], {%1,%2,%3,%4};"
                 :: "l"(p), "f"(v.x), "f"(v.y), "f"(v.z), "f"(v.w) : "memory");
    if (c == 0) atomicAdd(cnt + d, 1.0f);
}

// ---------------------------------------------------------------------------
struct alignas(16) SmemA {
    float W[3][D * D];     // W_id, W1, W2
    float Wp1[D * H];
    float b[3][D];
    float bp1[H];
    float Wp2[H];
    float X[TILE * 68];    // padded stride 68 (16B-aligned rows, bank shift)
    float Z[TILE * 68];
    float red[3][16];
};

__global__ __launch_bounds__(TPB_A, 1)
void k_passA(const float* __restrict__ h,
             const float* __restrict__ Wid, const float* __restrict__ bid,
             const float* __restrict__ W1,  const float* __restrict__ b1,
             const float* __restrict__ W2,  const float* __restrict__ b2,
             const float* __restrict__ Wp1, const float* __restrict__ bp1,
             const float* __restrict__ Wp2, int n) {
    extern __shared__ char smraw[];
    SmemA* sm = (SmemA*)smraw;
    const int t = threadIdx.x;
    const int ST = 68;

    // Load all weights into shared
    for (int i = t; i < D * D; i += TPB_A) {
        sm->W[0][i] = Wid[i]; sm->W[1][i] = W1[i]; sm->W[2][i] = W2[i];
    }
    for (int i = t; i < D * H; i += TPB_A) sm->Wp1[i] = Wp1[i];
    if (t < D) { sm->b[0][t] = bid[t]; sm->b[1][t] = b1[t]; sm->b[2][t] = b2[t]; }
    if (t < H) { sm->bp1[t] = bp1[t]; sm->Wp2[t] = Wp2[t]; }

    const int node0 = blockIdx.x * TILE;
    const int tc = t & 15;    // 16 col-groups
    const int tr = t >> 4;    // 32 row-groups of 4 rows
    bool rv[4];
#pragma unroll
    for (int r = 0; r < 4; r++) rv[r] = (node0 + tr * 4 + r) < n;

    float pw[3] = {0.f, 0.f, 0.f};

    for (int p = 0; p < 3; p++) {
        __syncthreads();
        // --- fill X tile (h for p=0, agg*inv_deg for p=1,2) ---
        for (int i = t; i < TILE * 16; i += TPB_A) {
            int row = i >> 4, c4 = i & 15;
            int node = node0 + row;
            float4 v = make_float4(0.f, 0.f, 0.f, 0.f);
            if (node < n) {
                if (p == 0) {
                    v = ((const float4*)h)[(size_t)node * 16 + c4];
                } else {
                    const float* agg = (p == 1) ? g_agg1 : g_agg2;
                    const float* cnt = (p == 1) ? g_cnt1 : g_cnt2;
                    float cv = cnt[node];
                    float inv = (cv > 0.f) ? 1.f / cv : 0.f;
                    float4 a = ((const float4*)agg)[(size_t)node * 16 + c4];
                    v = make_float4(a.x * inv, a.y * inv, a.z * inv, a.w * inv);
                }
            }
            *(float4*)&sm->X[row * ST + c4 * 4] = v;
        }
        __syncthreads();

        // --- GEMM1: Z = X @ W[p] + b[p]  (ELU for p>0); store z plane ---
        {
            float acc[4][4];
#pragma unroll
            for (int r = 0; r < 4; r++)
#pragma unroll
                for (int c = 0; c < 4; c++) acc[r][c] = 0.f;
            const float* Wp = sm->W[p];
#pragma unroll 8
            for (int k = 0; k < 64; k++) {
                float4 w = *(const float4*)&Wp[k * 64 + tc * 4];
#pragma unroll
                for (int r = 0; r < 4; r++) {
                    float a = sm->X[(tr * 4 + r) * ST + k];
                    acc[r][0] += a * w.x; acc[r][1] += a * w.y;
                    acc[r][2] += a * w.z; acc[r][3] += a * w.w;
                }
            }
#pragma unroll
            for (int r = 0; r < 4; r++) {
                int row = tr * 4 + r;
                float4 o;
                o.x = acc[r][0] + sm->b[p][tc * 4 + 0];
                o.y = acc[r][1] + sm->b[p][tc * 4 + 1];
                o.z = acc[r][2] + sm->b[p][tc * 4 + 2];
                o.w = acc[r][3] + sm->b[p][tc * 4 + 3];
                if (p > 0) {
                    o.x = (o.x > 0.f) ? o.x : expm1f(o.x);
                    o.y = (o.y > 0.f) ? o.y : expm1f(o.y);
                    o.z = (o.z > 0.f) ? o.z : expm1f(o.z);
                    o.w = (o.w > 0.f) ? o.w : expm1f(o.w);
                }
                *(float4*)&sm->Z[row * ST + tc * 4] = o;
                if (rv[r]) {
                    size_t off = ((size_t)p * n + (node0 + row)) * 64 + tc * 4;
                    *(float4*)&g_z[off] = o;
                }
            }
        }
        __syncthreads();

        // --- GEMM2: S = Z @ Wp1 + bp1; pw[p] += sum(tanh(S) * Wp2) over valid rows ---
        {
            float s[4][8];
#pragma unroll
            for (int r = 0; r < 4; r++)
#pragma unroll
                for (int c = 0; c < 8; c++) s[r][c] = 0.f;
#pragma unroll 8
            for (int k = 0; k < 64; k++) {
                float4 w0 = *(const float4*)&sm->Wp1[k * 128 + tc * 8];
                float4 w1 = *(const float4*)&sm->Wp1[k * 128 + tc * 8 + 4];
#pragma unroll
                for (int r = 0; r < 4; r++) {
                    float a = sm->Z[(tr * 4 + r) * ST + k];
                    s[r][0] += a * w0.x; s[r][1] += a * w0.y;
                    s[r][2] += a * w0.z; s[r][3] += a * w0.w;
                    s[r][4] += a * w1.x; s[r][5] += a * w1.y;
                    s[r][6] += a * w1.z; s[r][7] += a * w1.w;
                }
            }
            float wp2l[8], bpl[8];
#pragma unroll
            for (int c = 0; c < 8; c++) {
                wp2l[c] = sm->Wp2[tc * 8 + c];
                bpl[c]  = sm->bp1[tc * 8 + c];
            }
            float acc = 0.f;
#pragma unroll
            for (int r = 0; r < 4; r++) {
                if (!rv[r]) continue;
                float ra = 0.f;
#pragma unroll
                for (int c = 0; c < 8; c++) {
                    float x = s[r][c] + bpl[c];
                    float th;
                    asm("tanh.approx.f32 %0, %1;" : "=f"(th) : "f"(x));
                    ra += th * wp2l[c];
                }
                acc += ra;
            }
            pw[p] = acc;
        }
    }

    // --- block reduce pw[3], one atomicAdd each ---
    __syncthreads();
    int lane = t & 31, warp = t >> 5;
#pragma unroll
    for (int p = 0; p < 3; p++) {
        float v = pw[p];
        for (int o = 16; o; o >>= 1) v += __shfl_xor_sync(0xffffffffu, v, o);
        if (lane == 0) sm->red[p][warp] = v;
    }
    __syncthreads();
    if (warp == 0) {
#pragma unroll
        for (int p = 0; p < 3; p++) {
            float v = (lane < 16) ? sm->red[p][lane] : 0.f;
            for (int o = 8; o; o >>= 1) v += __shfl_xor_sync(0xffffffffu, v, o);
            if (lane == 0) atomicAdd(&g_wpart[p], v);
        }
    }
}

// ---------------------------------------------------------------------------
__global__ void k_out(float* __restrict__ out, int n) {
    int t = blockIdx.x * blockDim.x + threadIdx.x;
    int tot = n * 16;
    if (t >= tot) return;
    float fn = (float)n;
    float w0 = g_wpart[0] / fn, w1 = g_wpart[1] / fn, w2 = g_wpart[2] / fn;
    float m = fmaxf(w0, fmaxf(w1, w2));
    float e0 = expf(w0 - m), e1 = expf(w1 - m), e2 = expf(w2 - m);
    float inv = 1.f / (e0 + e1 + e2);
    float b0 = e0 * inv, b1 = e1 * inv, b2 = e2 * inv;
    const float4* z = (const float4*)g_z;
    size_t pl = (size_t)n * 16;
    float4 a = z[t], b = z[pl + t], c = z[2 * pl + t];
    float4 o;
    o.x = b0 * a.x + b1 * b.x + b2 * c.x;
    o.y = b0 * a.y + b1 * b.y + b2 * c.y;
    o.z = b0 * a.z + b1 * b.z + b2 * c.z;
    o.w = b0 * a.w + b1 * b.w + b2 * c.w;
    ((float4*)out)[t] = o;
}

// ---------------------------------------------------------------------------
extern "C" void kernel_launch(void* const* d_in, const int* in_sizes, int n_in,
                              void* d_out, int out_size) {
    const float* h   = (const float*)d_in[0];
    const int*   s1  = (const int*)d_in[1];
    const int*   d1  = (const int*)d_in[2];
    const int*   s2  = (const int*)d_in[3];
    const int*   d2  = (const int*)d_in[4];
    const float* Wid = (const float*)d_in[5];
    const float* bid = (const float*)d_in[6];
    const float* W1  = (const float*)d_in[7];
    const float* b1  = (const float*)d_in[8];
    const float* W2  = (const float*)d_in[9];
    const float* b2  = (const float*)d_in[10];
    const float* Wp1 = (const float*)d_in[11];
    const float* bp1 = (const float*)d_in[12];
    const float* Wp2 = (const float*)d_in[13];

    int n = in_sizes[0] / D;   // 200000
    int E = in_sizes[1];       // 1000000

    cudaFuncSetAttribute(k_passA, cudaFuncAttributeMaxDynamicSharedMemorySize,
                         (int)sizeof(SmemA));

    int tz = (n * 16 + 255) / 256;
    k_zero<<<tz, 256>>>(n);

    long long totS = (long long)2 * E * 16;
    k_scatter<<<(int)((totS + 255) / 256), 256>>>(h, s1, d1, s2, d2, E);

    k_passA<<<(n + TILE - 1) / TILE, TPB_A, sizeof(SmemA)>>>(
        h, Wid, bid, W1, b1, W2, b2, Wp1, bp1, Wp2, n);

    k_out<<<(n * 16 + 255) / 256, 256>>>((float*)d_out, n);
}

// round 5
// speedup vs baseline: 1.9209x; 1.9209x over previous
#include <cuda_runtime.h>
#include <cuda_bf16.h>
#include <math.h>
#include <stdint.h>

#define N_NODES 200000
#define D 64
#define H 128
#define TILE 128

// ---------------- device scratch ------------------------------------------
__device__ float g_agg1[(size_t)N_NODES * D];
__device__ float g_agg2[(size_t)N_NODES * D];
__device__ float g_cnt1[N_NODES];
__device__ float g_cnt2[N_NODES];
__device__ float g_z[(size_t)3 * N_NODES * D];
__device__ float g_wpart[3];
// Pre-converted bf16 weights in [n][k] layout, row stride 72 bf16:
//   plane p (W^T): hi @ bf16-idx p*9216, lo @ p*9216+4608   (p=0,1,2)
//   Wp1^T (hi only) @ bf16-idx 27648, 128 rows
__device__ __align__(16) __nv_bfloat16 g_prep[36864];

// ---------------- SMEM layout (bytes) -------------------------------------
#define SM_XHI   0        // 18432: X hi (stride 72 bf16) — reused as z-bf16 tile
#define SM_XLO   18432    // 18432: X lo
#define SM_B2    36864    // 55296: 3 planes (hi 9216 + lo 9216 each)
#define SM_B3    92160    // 18432: Wp1^T hi
#define SM_BIAS  110592   // 192 floats
#define SM_BP1   111360   // 128 floats
#define SM_WP2   111872   // 128 floats
#define SMEM_TOTAL 112640

// ---------------- helpers --------------------------------------------------
__device__ __forceinline__ uint32_t pkhi(float a, float b, float& la, float& lb) {
    __nv_bfloat16 ha = __float2bfloat16_rn(a), hb = __float2bfloat16_rn(b);
    la = a - __bfloat162float(ha);
    lb = b - __bfloat162float(hb);
    return (uint32_t)__bfloat16_as_ushort(ha) | ((uint32_t)__bfloat16_as_ushort(hb) << 16);
}
__device__ __forceinline__ uint32_t pk2(float a, float b) {
    return (uint32_t)__bfloat16_as_ushort(__float2bfloat16_rn(a)) |
           ((uint32_t)__bfloat16_as_ushort(__float2bfloat16_rn(b)) << 16);
}
__device__ __forceinline__ void mma16816(float* d, const uint32_t* a, const uint32_t* b) {
    asm volatile("mma.sync.aligned.m16n8k16.row.col.f32.bf16.bf16.f32 "
                 "{%0,%1,%2,%3}, {%4,%5,%6,%7}, {%8,%9}, {%0,%1,%2,%3};"
                 : "+f"(d[0]), "+f"(d[1]), "+f"(d[2]), "+f"(d[3])
                 : "r"(a[0]), "r"(a[1]), "r"(a[2]), "r"(a[3]), "r"(b[0]), "r"(b[1]));
}
__device__ __forceinline__ float tanha(float x) {
    float th;
    asm("tanh.approx.f32 %0, %1;" : "=f"(th) : "f"(x));
    return th;
}

// ---------------------------------------------------------------------------
__global__ void k_zero(int n) {
    int i = blockIdx.x * blockDim.x + threadIdx.x;
    int tot4 = n * (D / 4);
    if (i < tot4) {
        ((float4*)g_agg1)[i] = make_float4(0.f, 0.f, 0.f, 0.f);
        ((float4*)g_agg2)[i] = make_float4(0.f, 0.f, 0.f, 0.f);
    }
    if (i < n) { g_cnt1[i] = 0.f; g_cnt2[i] = 0.f; }
    if (i < 3) g_wpart[i] = 0.f;
}

// ---------------------------------------------------------------------------
__global__ void k_prep(const float* __restrict__ Wid, const float* __restrict__ W1,
                       const float* __restrict__ W2, const float* __restrict__ Wp1) {
    int t = threadIdx.x;
    for (int i = t; i < 3 * 4096; i += 256) {
        int p = i >> 12, rem = i & 4095;
        int k = rem >> 6, n2 = rem & 63;
        const float* W = (p == 0) ? Wid : (p == 1) ? W1 : W2;
        float v = W[k * 64 + n2];
        __nv_bfloat16 hb = __float2bfloat16_rn(v);
        float lo = v - __bfloat162float(hb);
        g_prep[p * 9216 + n2 * 72 + k] = hb;
        g_prep[p * 9216 + 4608 + n2 * 72 + k] = __float2bfloat16_rn(lo);
    }
    for (int i = t; i < 8192; i += 256) {
        int k = i >> 7, n2 = i & 127;
        g_prep[27648 + n2 * 72 + k] = __float2bfloat16_rn(Wp1[k * 128 + n2]);
    }
}

// ---------------------------------------------------------------------------
// which==0 -> agg1/cnt1, which==1 -> agg2/cnt2 (selected IN DEVICE CODE).
__global__ void k_scatter(const float* __restrict__ h,
                          const int* __restrict__ src, const int* __restrict__ dst,
                          int E, int which) {
    int t = blockIdx.x * blockDim.x + threadIdx.x;
    int e = t >> 4;
    int c = t & 15;
    if (e >= E) return;
    float* agg = which ? g_agg2 : g_agg1;
    float* cnt = which ? g_cnt2 : g_cnt1;
    int s = src[e], d = dst[e];
    float4 v = ((const float4*)h)[(size_t)s * 16 + c];
    float* p = agg + (size_t)d * 64 + c * 4;
    asm volatile("red.global.add.v4.f32 [%0], {%1,%2,%3,%4};"
                 :: "l"(p), "f"(v.x), "f"(v.y), "f"(v.z), "f"(v.w) : "memory");
    if (c == 0) atomicAdd(cnt + d, 1.0f);
}

// ---------------------------------------------------------------------------
__global__ __launch_bounds__(128, 2)
void k_passA(const float* __restrict__ h,
             const float* __restrict__ bid, const float* __restrict__ b1,
             const float* __restrict__ b2,  const float* __restrict__ bp1,
             const float* __restrict__ wp2, int nn) {
    extern __shared__ unsigned char sm[];
    uint32_t* Xhi = (uint32_t*)(sm + SM_XHI);   // also the z-bf16 tile
    uint32_t* Xlo = (uint32_t*)(sm + SM_XLO);
    const uint32_t* B3 = (const uint32_t*)(sm + SM_B3);
    float* sbias = (float*)(sm + SM_BIAS);
    float* sbp1  = (float*)(sm + SM_BP1);
    float* swp2  = (float*)(sm + SM_WP2);

    const int t = threadIdx.x;
    const int lid = t & 31, w = t >> 5;
    const int g4 = lid >> 2, tid = lid & 3;
    const int m0 = w * 32;
    const int node0 = blockIdx.x * TILE;

    // copy prepped weights (73728 B) + biases
    {
        const uint4* gp = (const uint4*)g_prep;
        uint4* sp = (uint4*)(sm + SM_B2);
        for (int i = t; i < 4608; i += 128) sp[i] = gp[i];
    }
    if (t < 64) { sbias[t] = bid[t]; sbias[64 + t] = b1[t]; sbias[128 + t] = b2[t]; }
    if (t < 128) { sbp1[t] = bp1[t]; swp2[t] = wp2[t]; }
    __syncthreads();

    float pw[3];

    for (int p = 0; p < 3; p++) {
        // ---- X fill: thread t -> row t (FULL 64 floats -> hi/lo bf16) -----
        {
            int node = node0 + t;
            bool valid = node < nn;
            const float* srcp = h;
            float inv = 1.f;
            if (valid) {
                if (p == 0) {
                    srcp = h + (size_t)node * 64;
                } else {
                    const float* agg = (p == 1) ? g_agg1 : g_agg2;
                    float cv = ((p == 1) ? g_cnt1 : g_cnt2)[node];
                    inv = (cv > 0.f) ? 1.f / cv : 0.f;
                    srcp = agg + (size_t)node * 64;
                }
            }
            const float4* s4 = (const float4*)srcp;
#pragma unroll
            for (int q = 0; q < 8; q++) {
                float4 a0, a1;
                if (valid) { a0 = s4[2 * q]; a1 = s4[2 * q + 1]; }
                else { a0 = make_float4(0.f,0.f,0.f,0.f); a1 = a0; }
                float x[8] = { a0.x*inv, a0.y*inv, a0.z*inv, a0.w*inv,
                               a1.x*inv, a1.y*inv, a1.z*inv, a1.w*inv };
                float l[8];
                uint32_t hu[4], lu[4];
#pragma unroll
                for (int i = 0; i < 4; i++)
                    hu[i] = pkhi(x[2*i], x[2*i+1], l[2*i], l[2*i+1]);
#pragma unroll
                for (int i = 0; i < 4; i++) lu[i] = pk2(l[2*i], l[2*i+1]);
                // row t, words 4q..4q+3 (t*36 % 4 == 0 -> 16B aligned)
                *(uint4*)&Xhi[t * 36 + 4 * q] = make_uint4(hu[0], hu[1], hu[2], hu[3]);
                *(uint4*)&Xlo[t * 36 + 4 * q] = make_uint4(lu[0], lu[1], lu[2], lu[3]);
            }
        }
        __syncwarp();

        // ---- GEMM1: acc[2][8][4] = X @ W^T (split bf16, 3 passes) ---------
        float acc[2][8][4];
#pragma unroll
        for (int mt = 0; mt < 2; mt++)
#pragma unroll
            for (int nt = 0; nt < 8; nt++)
#pragma unroll
                for (int i = 0; i < 4; i++) acc[mt][nt][i] = 0.f;

        const uint32_t* Bh = (const uint32_t*)(sm + SM_B2 + p * 18432);
        const uint32_t* Bl = (const uint32_t*)(sm + SM_B2 + p * 18432 + 9216);
#pragma unroll
        for (int ks = 0; ks < 4; ks++) {
            int kw = ks * 8;
            uint32_t ah[2][4], al[2][4];
#pragma unroll
            for (int mt = 0; mt < 2; mt++) {
                int base = (m0 + mt * 16 + g4) * 36 + kw + tid;
                ah[mt][0] = Xhi[base];       ah[mt][1] = Xhi[base + 288];
                ah[mt][2] = Xhi[base + 4];   ah[mt][3] = Xhi[base + 292];
                al[mt][0] = Xlo[base];       al[mt][1] = Xlo[base + 288];
                al[mt][2] = Xlo[base + 4];   al[mt][3] = Xlo[base + 292];
            }
#pragma unroll
            for (int nt = 0; nt < 8; nt++) {
                int nb = (nt * 8 + g4) * 36 + kw + tid;
                uint32_t bh[2] = { Bh[nb], Bh[nb + 4] };
                uint32_t bl[2] = { Bl[nb], Bl[nb + 4] };
#pragma unroll
                for (int mt = 0; mt < 2; mt++) {
                    mma16816(acc[mt][nt], ah[mt], bh);
                    mma16816(acc[mt][nt], ah[mt], bl);
                    mma16816(acc[mt][nt], al[mt], bh);
                }
            }
        }
        __syncwarp();   // GEMM1 reads of Xhi done before epilogue overwrites

        // ---- epilogue1: bias/ELU, STG z fp32, STS z bf16 (into Xhi) -------
#pragma unroll
        for (int mt = 0; mt < 2; mt++) {
            int r = m0 + mt * 16 + g4;
            int nodeA = node0 + r, nodeB = nodeA + 8;
            bool vA = nodeA < nn, vB = nodeB < nn;
            float2* zA = (float2*)(g_z + ((size_t)p * nn + nodeA) * 64);
            float2* zB = (float2*)(g_z + ((size_t)p * nn + nodeB) * 64);
#pragma unroll
            for (int nt = 0; nt < 8; nt++) {
                int c = nt * 8 + tid * 2;
                float2 bb = *(float2*)&sbias[p * 64 + c];
                float v0 = acc[mt][nt][0] + bb.x;
                float v1 = acc[mt][nt][1] + bb.y;
                float v2 = acc[mt][nt][2] + bb.x;
                float v3 = acc[mt][nt][3] + bb.y;
                if (p > 0) {
                    v0 = (v0 > 0.f) ? v0 : expm1f(v0);
                    v1 = (v1 > 0.f) ? v1 : expm1f(v1);
                    v2 = (v2 > 0.f) ? v2 : expm1f(v2);
                    v3 = (v3 > 0.f) ? v3 : expm1f(v3);
                }
                if (vA) zA[nt * 4 + tid] = make_float2(v0, v1);
                if (vB) zB[nt * 4 + tid] = make_float2(v2, v3);
                Xhi[r * 36 + nt * 4 + tid]       = pk2(v0, v1);
                Xhi[(r + 8) * 36 + nt * 4 + tid] = pk2(v2, v3);
            }
        }
        __syncwarp();

        // ---- GEMM2 (bf16): S = z @ Wp1^T, two n-halves; reduce tanh*wp2 ---
        float pacc = 0.f;
#pragma unroll
        for (int hh = 0; hh < 2; hh++) {
            float a2c[2][8][4];
#pragma unroll
            for (int mt = 0; mt < 2; mt++)
#pragma unroll
                for (int nt = 0; nt < 8; nt++)
#pragma unroll
                    for (int i = 0; i < 4; i++) a2c[mt][nt][i] = 0.f;
#pragma unroll
            for (int ks = 0; ks < 4; ks++) {
                int kw = ks * 8;
                uint32_t a2[2][4];
#pragma unroll
                for (int mt = 0; mt < 2; mt++) {
                    int base = (m0 + mt * 16 + g4) * 36 + kw + tid;
                    a2[mt][0] = Xhi[base];     a2[mt][1] = Xhi[base + 288];
                    a2[mt][2] = Xhi[base + 4]; a2[mt][3] = Xhi[base + 292];
                }
#pragma unroll
                for (int nt = 0; nt < 8; nt++) {
                    int nb = (hh * 64 + nt * 8 + g4) * 36 + kw + tid;
                    uint32_t b[2] = { B3[nb], B3[nb + 4] };
#pragma unroll
                    for (int mt = 0; mt < 2; mt++) mma16816(a2c[mt][nt], a2[mt], b);
                }
            }
#pragma unroll
            for (int mt = 0; mt < 2; mt++) {
                int r = m0 + mt * 16 + g4;
                bool vA = (node0 + r) < nn, vB = (node0 + r + 8) < nn;
#pragma unroll
                for (int nt = 0; nt < 8; nt++) {
                    int c = hh * 64 + nt * 8 + tid * 2;
                    float2 bb = *(float2*)&sbp1[c];
                    float2 ww = *(float2*)&swp2[c];
                    if (vA) pacc += tanha(a2c[mt][nt][0] + bb.x) * ww.x
                                  + tanha(a2c[mt][nt][1] + bb.y) * ww.y;
                    if (vB) pacc += tanha(a2c[mt][nt][2] + bb.x) * ww.x
                                  + tanha(a2c[mt][nt][3] + bb.y) * ww.y;
                }
            }
        }
        pw[p] = pacc;
        __syncwarp();   // GEMM2 reads of Xhi done before next plane's fill
    }

    // ---- warp-reduce pw, one atomic per warp per plane ---------------------
#pragma unroll
    for (int p = 0; p < 3; p++) {
        float v = pw[p];
#pragma unroll
        for (int o = 16; o; o >>= 1) v += __shfl_xor_sync(0xffffffffu, v, o);
        if (lid == 0) atomicAdd(&g_wpart[p], v);
    }
}

// ---------------------------------------------------------------------------
__global__ void k_out(float* __restrict__ out, int n) {
    int t = blockIdx.x * blockDim.x + threadIdx.x;
    int tot = n * 16;
    if (t >= tot) return;
    float fn = (float)n;
    float w0 = g_wpart[0] / fn, w1 = g_wpart[1] / fn, w2 = g_wpart[2] / fn;
    float m = fmaxf(w0, fmaxf(w1, w2));
    float e0 = expf(w0 - m), e1 = expf(w1 - m), e2 = expf(w2 - m);
    float inv = 1.f / (e0 + e1 + e2);
    float b0 = e0 * inv, b1 = e1 * inv, b2 = e2 * inv;
    const float4* z = (const float4*)g_z;
    size_t pl = (size_t)n * 16;
    float4 a = z[t], b = z[pl + t], c = z[2 * pl + t];
    float4 o;
    o.x = b0 * a.x + b1 * b.x + b2 * c.x;
    o.y = b0 * a.y + b1 * b.y + b2 * c.y;
    o.z = b0 * a.z + b1 * b.z + b2 * c.z;
    o.w = b0 * a.w + b1 * b.w + b2 * c.w;
    ((float4*)out)[t] = o;
}

// ---------------------------------------------------------------------------
extern "C" void kernel_launch(void* const* d_in, const int* in_sizes, int n_in,
                              void* d_out, int out_size) {
    const float* h   = (const float*)d_in[0];
    const int*   s1  = (const int*)d_in[1];
    const int*   d1  = (const int*)d_in[2];
    const int*   s2  = (const int*)d_in[3];
    const int*   d2  = (const int*)d_in[4];
    const float* Wid = (const float*)d_in[5];
    const float* bid = (const float*)d_in[6];
    const float* W1  = (const float*)d_in[7];
    const float* b1  = (const float*)d_in[8];
    const float* W2  = (const float*)d_in[9];
    const float* b2  = (const float*)d_in[10];
    const float* Wp1 = (const float*)d_in[11];
    const float* bp1 = (const float*)d_in[12];
    const float* Wp2 = (const float*)d_in[13];

    int n = in_sizes[0] / D;   // 200000
    int E = in_sizes[1];       // 1000000

    cudaFuncSetAttribute(k_passA, cudaFuncAttributeMaxDynamicSharedMemorySize, SMEM_TOTAL);

    k_prep<<<1, 256>>>(Wid, W1, W2, Wp1);

    int tz = (n * 16 + 255) / 256;
    k_zero<<<tz, 256>>>(n);

    // two scatter kernels: each keeps (h + one agg) inside L2
    int gs = (E * 16 + 255) / 256;
    k_scatter<<<gs, 256>>>(h, s1, d1, E, 0);
    k_scatter<<<gs, 256>>>(h, s2, d2, E, 1);

    k_passA<<<(n + TILE - 1) / TILE, 128, SMEM_TOTAL>>>(h, bid, b1, b2, bp1, Wp2, n);

    k_out<<<(n * 16 + 255) / 256, 256>>>((float*)d_out, n);
}

// round 7
// speedup vs baseline: 2.1778x; 1.1337x over previous
#include <cuda_runtime.h>
#include <cuda_bf16.h>
#include <math.h>
#include <stdint.h>

#define N_NODES 200000
#define D 64
#define H 128
#define TILE 128

// ---------------- device scratch ------------------------------------------
__device__ float g_agg1[(size_t)N_NODES * D];
__device__ float g_agg2[(size_t)N_NODES * D];
__device__ float g_cnt1[N_NODES];
__device__ float g_cnt2[N_NODES];
__device__ float g_z[(size_t)3 * N_NODES * D];
__device__ float g_wpart[3];
// Pre-converted bf16 weights in [n][k] layout, row stride 72 bf16:
//   plane p (W^T): hi @ bf16-idx p*9216, lo @ p*9216+4608   (p=0,1,2)
//   Wp1^T (hi only) @ bf16-idx 27648, 128 rows
__device__ __align__(16) __nv_bfloat16 g_prep[36864];

// ---------------- SMEM layout (bytes) -------------------------------------
#define SM_XHI   0        // 18432: X hi (stride 72 bf16) — reused as z-bf16 tile
#define SM_XLO   18432    // 18432: X lo
#define SM_B2    36864    // 55296: 3 planes (hi 9216 + lo 9216 each)
#define SM_B3    92160    // 18432: Wp1^T hi
#define SM_BIAS  110592   // 192 floats
#define SM_BP1   111360   // 128 floats
#define SM_WP2   111872   // 128 floats
#define SMEM_TOTAL 112640

// ---------------- helpers --------------------------------------------------
__device__ __forceinline__ uint32_t pkhi(float a, float b, float& la, float& lb) {
    __nv_bfloat16 ha = __float2bfloat16_rn(a), hb = __float2bfloat16_rn(b);
    la = a - __bfloat162float(ha);
    lb = b - __bfloat162float(hb);
    return (uint32_t)__bfloat16_as_ushort(ha) | ((uint32_t)__bfloat16_as_ushort(hb) << 16);
}
__device__ __forceinline__ uint32_t pk2(float a, float b) {
    return (uint32_t)__bfloat16_as_ushort(__float2bfloat16_rn(a)) |
           ((uint32_t)__bfloat16_as_ushort(__float2bfloat16_rn(b)) << 16);
}
__device__ __forceinline__ void mma16816(float* d, const uint32_t* a, const uint32_t* b) {
    asm volatile("mma.sync.aligned.m16n8k16.row.col.f32.bf16.bf16.f32 "
                 "{%0,%1,%2,%3}, {%4,%5,%6,%7}, {%8,%9}, {%0,%1,%2,%3};"
                 : "+f"(d[0]), "+f"(d[1]), "+f"(d[2]), "+f"(d[3])
                 : "r"(a[0]), "r"(a[1]), "r"(a[2]), "r"(a[3]), "r"(b[0]), "r"(b[1]));
}
__device__ __forceinline__ float tanha(float x) {
    float th;
    asm("tanh.approx.f32 %0, %1;" : "=f"(th) : "f"(x));
    return th;
}
// Fast ELU: exp(x)-1 via ex2.approx (MUFU), ~4 ops vs ~25 for expm1f.
__device__ __forceinline__ float elu(float v) {
    float e;
    asm("ex2.approx.f32 %0, %1;" : "=f"(e) : "f"(v * 1.4426950408889634f));
    return (v > 0.f) ? v : (e - 1.f);
}

// ---------------------------------------------------------------------------
__global__ void k_zero(int n) {
    int i = blockIdx.x * blockDim.x + threadIdx.x;
    int tot4 = n * (D / 4);
    if (i < tot4) {
        ((float4*)g_agg1)[i] = make_float4(0.f, 0.f, 0.f, 0.f);
        ((float4*)g_agg2)[i] = make_float4(0.f, 0.f, 0.f, 0.f);
    }
    if (i < n) { g_cnt1[i] = 0.f; g_cnt2[i] = 0.f; }
    if (i < 3) g_wpart[i] = 0.f;
}

// ---------------------------------------------------------------------------
__global__ void k_prep(const float* __restrict__ Wid, const float* __restrict__ W1,
                       const float* __restrict__ W2, const float* __restrict__ Wp1) {
    int t = threadIdx.x;
    for (int i = t; i < 3 * 4096; i += 256) {
        int p = i >> 12, rem = i & 4095;
        int k = rem >> 6, n2 = rem & 63;
        const float* W = (p == 0) ? Wid : (p == 1) ? W1 : W2;
        float v = W[k * 64 + n2];
        __nv_bfloat16 hb = __float2bfloat16_rn(v);
        float lo = v - __bfloat162float(hb);
        g_prep[p * 9216 + n2 * 72 + k] = hb;
        g_prep[p * 9216 + 4608 + n2 * 72 + k] = __float2bfloat16_rn(lo);
    }
    for (int i = t; i < 8192; i += 256) {
        int k = i >> 7, n2 = i & 127;
        g_prep[27648 + n2 * 72 + k] = __float2bfloat16_rn(Wp1[k * 128 + n2]);
    }
}

// ---------------------------------------------------------------------------
// Single merged scatter over both edge lists (device-side buffer select)
// -> doubles memory-level parallelism for the latency-bound h[src] gather.
__global__ void k_scatter(const float* __restrict__ h,
                          const int* __restrict__ s1, const int* __restrict__ d1,
                          const int* __restrict__ s2, const int* __restrict__ d2,
                          int E) {
    int t = blockIdx.x * blockDim.x + threadIdx.x;
    int e = t >> 4;
    int c = t & 15;
    if (e >= 2 * E) return;
    const int* sp; const int* dp; float* agg; float* cnt;
    if (e < E) { sp = s1; dp = d1; agg = g_agg1; cnt = g_cnt1; }
    else       { e -= E; sp = s2; dp = d2; agg = g_agg2; cnt = g_cnt2; }
    int s = sp[e], d = dp[e];
    float4 v = ((const float4*)h)[(size_t)s * 16 + c];
    float* p = agg + (size_t)d * 64 + c * 4;
    asm volatile("red.global.add.v4.f32 [%0], {%1,%2,%3,%4};"
                 :: "l"(p), "f"(v.x), "f"(v.y), "f"(v.z), "f"(v.w) : "memory");
    if (c == 0) atomicAdd(cnt + d, 1.0f);
}

// ---------------------------------------------------------------------------
__global__ __launch_bounds__(128, 2)
void k_passA(const float* __restrict__ h,
             const float* __restrict__ bid, const float* __restrict__ b1,
             const float* __restrict__ b2,  const float* __restrict__ bp1,
             const float* __restrict__ wp2, int nn) {
    extern __shared__ unsigned char sm[];
    uint32_t* Xhi = (uint32_t*)(sm + SM_XHI);   // also the z-bf16 tile
    uint32_t* Xlo = (uint32_t*)(sm + SM_XLO);
    const uint32_t* B3 = (const uint32_t*)(sm + SM_B3);
    float* sbias = (float*)(sm + SM_BIAS);
    float* sbp1  = (float*)(sm + SM_BP1);
    float* swp2  = (float*)(sm + SM_WP2);

    const int t = threadIdx.x;
    const int lid = t & 31, w = t >> 5;
    const int g4 = lid >> 2, tid = lid & 3;
    const int m0 = w * 32;
    const int node0 = blockIdx.x * TILE;

    // copy prepped weights (73728 B) + biases
    {
        const uint4* gp = (const uint4*)g_prep;
        uint4* sp = (uint4*)(sm + SM_B2);
        for (int i = t; i < 4608; i += 128) sp[i] = gp[i];
    }
    if (t < 64) { sbias[t] = bid[t]; sbias[64 + t] = b1[t]; sbias[128 + t] = b2[t]; }
    if (t < 128) { sbp1[t] = bp1[t]; swp2[t] = wp2[t]; }
    __syncthreads();

    float pw[3];

    for (int p = 0; p < 3; p++) {
        // ---- X fill: thread t -> row t (FULL 64 floats -> hi/lo bf16) -----
        {
            int node = node0 + t;
            bool valid = node < nn;
            const float* srcp = h;
            float inv = 1.f;
            if (valid) {
                if (p == 0) {
                    srcp = h + (size_t)node * 64;
                } else {
                    const float* agg = (p == 1) ? g_agg1 : g_agg2;
                    float cv = ((p == 1) ? g_cnt1 : g_cnt2)[node];
                    inv = (cv > 0.f) ? 1.f / cv : 0.f;
                    srcp = agg + (size_t)node * 64;
                }
            }
            const float4* s4 = (const float4*)srcp;
#pragma unroll
            for (int q = 0; q < 8; q++) {
                float4 a0, a1;
                if (valid) { a0 = s4[2 * q]; a1 = s4[2 * q + 1]; }
                else { a0 = make_float4(0.f,0.f,0.f,0.f); a1 = a0; }
                float x[8] = { a0.x*inv, a0.y*inv, a0.z*inv, a0.w*inv,
                               a1.x*inv, a1.y*inv, a1.z*inv, a1.w*inv };
                float l[8];
                uint32_t hu[4], lu[4];
#pragma unroll
                for (int i = 0; i < 4; i++)
                    hu[i] = pkhi(x[2*i], x[2*i+1], l[2*i], l[2*i+1]);
#pragma unroll
                for (int i = 0; i < 4; i++) lu[i] = pk2(l[2*i], l[2*i+1]);
                *(uint4*)&Xhi[t * 36 + 4 * q] = make_uint4(hu[0], hu[1], hu[2], hu[3]);
                *(uint4*)&Xlo[t * 36 + 4 * q] = make_uint4(lu[0], lu[1], lu[2], lu[3]);
            }
        }
        __syncwarp();

        // ---- GEMM1: acc[2][8][4] = X @ W^T (split bf16, 3 passes) ---------
        float acc[2][8][4];
#pragma unroll
        for (int mt = 0; mt < 2; mt++)
#pragma unroll
            for (int nt = 0; nt < 8; nt++)
#pragma unroll
                for (int i = 0; i < 4; i++) acc[mt][nt][i] = 0.f;

        const uint32_t* Bh = (const uint32_t*)(sm + SM_B2 + p * 18432);
        const uint32_t* Bl = (const uint32_t*)(sm + SM_B2 + p * 18432 + 9216);
#pragma unroll
        for (int ks = 0; ks < 4; ks++) {
            int kw = ks * 8;
            uint32_t ah[2][4], al[2][4];
#pragma unroll
            for (int mt = 0; mt < 2; mt++) {
                int base = (m0 + mt * 16 + g4) * 36 + kw + tid;
                ah[mt][0] = Xhi[base];       ah[mt][1] = Xhi[base + 288];
                ah[mt][2] = Xhi[base + 4];   ah[mt][3] = Xhi[base + 292];
                al[mt][0] = Xlo[base];       al[mt][1] = Xlo[base + 288];
                al[mt][2] = Xlo[base + 4];   al[mt][3] = Xlo[base + 292];
            }
#pragma unroll
            for (int nt = 0; nt < 8; nt++) {
                int nb = (nt * 8 + g4) * 36 + kw + tid;
                uint32_t bh[2] = { Bh[nb], Bh[nb + 4] };
                uint32_t bl[2] = { Bl[nb], Bl[nb + 4] };
#pragma unroll
                for (int mt = 0; mt < 2; mt++) {
                    mma16816(acc[mt][nt], ah[mt], bh);
                    mma16816(acc[mt][nt], ah[mt], bl);
                    mma16816(acc[mt][nt], al[mt], bh);
                }
            }
        }
        __syncwarp();   // GEMM1 reads of Xhi done before epilogue overwrites

        // ---- epilogue1: bias/ELU, STG z fp32, STS z bf16 (into Xhi) -------
#pragma unroll
        for (int mt = 0; mt < 2; mt++) {
            int r = m0 + mt * 16 + g4;
            int nodeA = node0 + r, nodeB = nodeA + 8;
            bool vA = nodeA < nn, vB = nodeB < nn;
            float2* zA = (float2*)(g_z + ((size_t)p * nn + nodeA) * 64);
            float2* zB = (float2*)(g_z + ((size_t)p * nn + nodeB) * 64);
#pragma unroll
            for (int nt = 0; nt < 8; nt++) {
                int c = nt * 8 + tid * 2;
                float2 bb = *(float2*)&sbias[p * 64 + c];
                float v0 = acc[mt][nt][0] + bb.x;
                float v1 = acc[mt][nt][1] + bb.y;
                float v2 = acc[mt][nt][2] + bb.x;
                float v3 = acc[mt][nt][3] + bb.y;
                if (p > 0) {
                    v0 = elu(v0); v1 = elu(v1); v2 = elu(v2); v3 = elu(v3);
                }
                if (vA) zA[nt * 4 + tid] = make_float2(v0, v1);
                if (vB) zB[nt * 4 + tid] = make_float2(v2, v3);
                Xhi[r * 36 + nt * 4 + tid]       = pk2(v0, v1);
                Xhi[(r + 8) * 36 + nt * 4 + tid] = pk2(v2, v3);
            }
        }
        __syncwarp();

        // ---- GEMM2 (bf16): S = z @ Wp1^T, two n-halves; reduce tanh*wp2 ---
        float pacc = 0.f;
#pragma unroll
        for (int hh = 0; hh < 2; hh++) {
            float a2c[2][8][4];
#pragma unroll
            for (int mt = 0; mt < 2; mt++)
#pragma unroll
                for (int nt = 0; nt < 8; nt++)
#pragma unroll
                    for (int i = 0; i < 4; i++) a2c[mt][nt][i] = 0.f;
#pragma unroll
            for (int ks = 0; ks < 4; ks++) {
                int kw = ks * 8;
                uint32_t a2[2][4];
#pragma unroll
                for (int mt = 0; mt < 2; mt++) {
                    int base = (m0 + mt * 16 + g4) * 36 + kw + tid;
                    a2[mt][0] = Xhi[base];     a2[mt][1] = Xhi[base + 288];
                    a2[mt][2] = Xhi[base + 4]; a2[mt][3] = Xhi[base + 292];
                }
#pragma unroll
                for (int nt = 0; nt < 8; nt++) {
                    int nb = (hh * 64 + nt * 8 + g4) * 36 + kw + tid;
                    uint32_t b[2] = { B3[nb], B3[nb + 4] };
#pragma unroll
                    for (int mt = 0; mt < 2; mt++) mma16816(a2c[mt][nt], a2[mt], b);
                }
            }
#pragma unroll
            for (int mt = 0; mt < 2; mt++) {
                int r = m0 + mt * 16 + g4;
                bool vA = (node0 + r) < nn, vB = (node0 + r + 8) < nn;
#pragma unroll
                for (int nt = 0; nt < 8; nt++) {
                    int c = hh * 64 + nt * 8 + tid * 2;
                    float2 bb = *(float2*)&sbp1[c];
                    float2 ww = *(float2*)&swp2[c];
                    if (vA) pacc += tanha(a2c[mt][nt][0] + bb.x) * ww.x
                                  + tanha(a2c[mt][nt][1] + bb.y) * ww.y;
                    if (vB) pacc += tanha(a2c[mt][nt][2] + bb.x) * ww.x
                                  + tanha(a2c[mt][nt][3] + bb.y) * ww.y;
                }
            }
        }
        pw[p] = pacc;
        __syncwarp();   // GEMM2 reads of Xhi done before next plane's fill
    }

    // ---- warp-reduce pw, one atomic per warp per plane ---------------------
#pragma unroll
    for (int p = 0; p < 3; p++) {
        float v = pw[p];
#pragma unroll
        for (int o = 16; o; o >>= 1) v += __shfl_xor_sync(0xffffffffu, v, o);
        if (lid == 0) atomicAdd(&g_wpart[p], v);
    }
}

// ---------------------------------------------------------------------------
__global__ void k_out(float* __restrict__ out, int n) {
    int t = blockIdx.x * blockDim.x + threadIdx.x;
    int tot = n * 16;
    if (t >= tot) return;
    float fn = (float)n;
    float w0 = g_wpart[0] / fn, w1 = g_wpart[1] / fn, w2 = g_wpart[2] / fn;
    float m = fmaxf(w0, fmaxf(w1, w2));
    float e0 = expf(w0 - m), e1 = expf(w1 - m), e2 = expf(w2 - m);
    float inv = 1.f / (e0 + e1 + e2);
    float b0 = e0 * inv, b1 = e1 * inv, b2 = e2 * inv;
    const float4* z = (const float4*)g_z;
    size_t pl = (size_t)n * 16;
    float4 a = z[t], b = z[pl + t], c = z[2 * pl + t];
    float4 o;
    o.x = b0 * a.x + b1 * b.x + b2 * c.x;
    o.y = b0 * a.y + b1 * b.y + b2 * c.y;
    o.z = b0 * a.z + b1 * b.z + b2 * c.z;
    o.w = b0 * a.w + b1 * b.w + b2 * c.w;
    ((float4*)out)[t] = o;
}

// ---------------------------------------------------------------------------
extern "C" void kernel_launch(void* const* d_in, const int* in_sizes, int n_in,
                              void* d_out, int out_size) {
    const float* h   = (const float*)d_in[0];
    const int*   s1  = (const int*)d_in[1];
    const int*   d1  = (const int*)d_in[2];
    const int*   s2  = (const int*)d_in[3];
    const int*   d2  = (const int*)d_in[4];
    const float* Wid = (const float*)d_in[5];
    const float* bid = (const float*)d_in[6];
    const float* W1  = (const float*)d_in[7];
    const float* b1  = (const float*)d_in[8];
    const float* W2  = (const float*)d_in[9];
    const float* b2  = (const float*)d_in[10];
    const float* Wp1 = (const float*)d_in[11];
    const float* bp1 = (const float*)d_in[12];
    const float* Wp2 = (const float*)d_in[13];

    int n = in_sizes[0] / D;   // 200000
    int E = in_sizes[1];       // 1000000

    cudaFuncSetAttribute(k_passA, cudaFuncAttributeMaxDynamicSharedMemorySize, SMEM_TOTAL);

    k_prep<<<1, 256>>>(Wid, W1, W2, Wp1);

    int tz = (n * 16 + 255) / 256;
    k_zero<<<tz, 256>>>(n);

    long long totS = (long long)2 * E * 16;
    k_scatter<<<(int)((totS + 255) / 256), 256>>>(h, s1, d1, s2, d2, E);

    k_passA<<<(n + TILE - 1) / TILE, 128, SMEM_TOTAL>>>(h, bid, b1, b2, bp1, Wp2, n);

    k_out<<<(n * 16 + 255) / 256, 256>>>((float*)d_out, n);
}

// round 8
// speedup vs baseline: 2.5441x; 1.1682x over previous
#include <cuda_runtime.h>
#include <cuda_bf16.h>
#include <math.h>
#include <stdint.h>

#define N_NODES 200000
#define D 64
#define H 128
#define TILE 128

// ---------------- device scratch ------------------------------------------
__device__ float g_agg1[(size_t)N_NODES * D];
__device__ float g_agg2[(size_t)N_NODES * D];
__device__ float g_cnt1[N_NODES];
__device__ float g_cnt2[N_NODES];
__device__ float g_z[(size_t)3 * N_NODES * D];
__device__ float g_wpart[3];
// Fragment-packed bf16 weights (built by k_prep), one warp-coalesced uint2
// per lane per (plane,ks,nt):
//   g_B1h/g_B1l: [3][4][8][32] — W^T hi/lo fragments for GEMM1
//   g_B3:        [2][4][8][32] — Wp1^T hi fragments for GEMM2 (hh halves)
__device__ __align__(16) uint2 g_B1h[3 * 4 * 8 * 32];
__device__ __align__(16) uint2 g_B1l[3 * 4 * 8 * 32];
__device__ __align__(16) uint2 g_B3[2 * 4 * 8 * 32];

// ---------------- SMEM layout (bytes) -------------------------------------
#define SM_XHI   0        // 18432: X hi (stride 72 bf16) — reused as z-bf16 tile
#define SM_XLO   18432    // 18432: X lo
#define SM_BIAS  36864    // 192 floats
#define SM_BP1   37632    // 128 floats
#define SM_WP2   38144    // 128 floats
#define SMEM_TOTAL 38656

// ---------------- helpers --------------------------------------------------
__device__ __forceinline__ uint32_t pkhi(float a, float b, float& la, float& lb) {
    __nv_bfloat16 ha = __float2bfloat16_rn(a), hb = __float2bfloat16_rn(b);
    la = a - __bfloat162float(ha);
    lb = b - __bfloat162float(hb);
    return (uint32_t)__bfloat16_as_ushort(ha) | ((uint32_t)__bfloat16_as_ushort(hb) << 16);
}
__device__ __forceinline__ uint32_t pk2(float a, float b) {
    return (uint32_t)__bfloat16_as_ushort(__float2bfloat16_rn(a)) |
           ((uint32_t)__bfloat16_as_ushort(__float2bfloat16_rn(b)) << 16);
}
__device__ __forceinline__ void mma16816(float* d, const uint32_t* a, uint2 b) {
    asm volatile("mma.sync.aligned.m16n8k16.row.col.f32.bf16.bf16.f32 "
                 "{%0,%1,%2,%3}, {%4,%5,%6,%7}, {%8,%9}, {%0,%1,%2,%3};"
                 : "+f"(d[0]), "+f"(d[1]), "+f"(d[2]), "+f"(d[3])
                 : "r"(a[0]), "r"(a[1]), "r"(a[2]), "r"(a[3]), "r"(b.x), "r"(b.y));
}
__device__ __forceinline__ float tanha(float x) {
    float th;
    asm("tanh.approx.f32 %0, %1;" : "=f"(th) : "f"(x));
    return th;
}
// Fast ELU via ex2.approx (MUFU).
__device__ __forceinline__ float elu(float v) {
    float e;
    asm("ex2.approx.f32 %0, %1;" : "=f"(e) : "f"(v * 1.4426950408889634f));
    return (v > 0.f) ? v : (e - 1.f);
}

// ---------------------------------------------------------------------------
__global__ void k_zero(int n) {
    int i = blockIdx.x * blockDim.x + threadIdx.x;
    int tot4 = n * (D / 4);
    if (i < tot4) {
        ((float4*)g_agg1)[i] = make_float4(0.f, 0.f, 0.f, 0.f);
        ((float4*)g_agg2)[i] = make_float4(0.f, 0.f, 0.f, 0.f);
    }
    if (i < n) { g_cnt1[i] = 0.f; g_cnt2[i] = 0.f; }
    if (i < 3) g_wpart[i] = 0.f;
}

// ---------------------------------------------------------------------------
// Build fragment-packed B arrays. Fragment mapping (must match passA):
//   GEMM1 b-frag for (p,ks,nt,lane): lane=g4*4+tid, n=nt*8+g4,
//     word0 = k-word (ks*8+tid)  -> bf16 pair (k=2w, 2w+1) of W^T row n
//     word1 = k-word (ks*8+tid+4)
//   W^T element (n,k) = W[k*64+n].
//   GEMM2: n = hh*64 + nt*8 + g4, element Wp1^T(n,k) = Wp1[k*128+n].
__global__ void k_prep(const float* __restrict__ Wid, const float* __restrict__ W1,
                       const float* __restrict__ W2, const float* __restrict__ Wp1) {
    int t = blockIdx.x * blockDim.x + threadIdx.x;
    for (int idx = t; idx < 3 * 4 * 8 * 32; idx += 512) {
        int p = idx >> 10, rem = idx & 1023;
        int ks = rem >> 8, rem2 = rem & 255;
        int nt = rem2 >> 5, lane = rem2 & 31;
        int g4 = lane >> 2, tid = lane & 3;
        int n = nt * 8 + g4;
        int w0 = ks * 8 + tid, w1 = w0 + 4;
        const float* W = (p == 0) ? Wid : (p == 1) ? W1 : W2;
        float a0 = W[(2 * w0) * 64 + n],     a1 = W[(2 * w0 + 1) * 64 + n];
        float b0 = W[(2 * w1) * 64 + n],     b1 = W[(2 * w1 + 1) * 64 + n];
        float la0, la1, lb0, lb1;
        uint32_t h0 = pkhi(a0, a1, la0, la1);
        uint32_t h1 = pkhi(b0, b1, lb0, lb1);
        g_B1h[idx] = make_uint2(h0, h1);
        g_B1l[idx] = make_uint2(pk2(la0, la1), pk2(lb0, lb1));
    }
    for (int idx = t; idx < 2 * 4 * 8 * 32; idx += 512) {
        int hh = idx >> 10, rem = idx & 1023;
        int ks = rem >> 8, rem2 = rem & 255;
        int nt = rem2 >> 5, lane = rem2 & 31;
        int g4 = lane >> 2, tid = lane & 3;
        int n = hh * 64 + nt * 8 + g4;
        int w0 = ks * 8 + tid, w1 = w0 + 4;
        g_B3[idx] = make_uint2(
            pk2(Wp1[(2 * w0) * 128 + n], Wp1[(2 * w0 + 1) * 128 + n]),
            pk2(Wp1[(2 * w1) * 128 + n], Wp1[(2 * w1 + 1) * 128 + n]));
    }
}

// ---------------------------------------------------------------------------
// Single merged scatter over both edge lists (device-side buffer select).
__global__ void k_scatter(const float* __restrict__ h,
                          const int* __restrict__ s1, const int* __restrict__ d1,
                          const int* __restrict__ s2, const int* __restrict__ d2,
                          int E) {
    int t = blockIdx.x * blockDim.x + threadIdx.x;
    int e = t >> 4;
    int c = t & 15;
    if (e >= 2 * E) return;
    const int* sp; const int* dp; float* agg; float* cnt;
    if (e < E) { sp = s1; dp = d1; agg = g_agg1; cnt = g_cnt1; }
    else       { e -= E; sp = s2; dp = d2; agg = g_agg2; cnt = g_cnt2; }
    int s = sp[e], d = dp[e];
    float4 v = ((const float4*)h)[(size_t)s * 16 + c];
    float* p = agg + (size_t)d * 64 + c * 4;
    asm volatile("red.global.add.v4.f32 [%0], {%1,%2,%3,%4};"
                 :: "l"(p), "f"(v.x), "f"(v.y), "f"(v.z), "f"(v.w) : "memory");
    if (c == 0) atomicAdd(cnt + d, 1.0f);
}

// ---------------------------------------------------------------------------
__global__ __launch_bounds__(128, 4)
void k_passA(const float* __restrict__ h,
             const float* __restrict__ bid, const float* __restrict__ b1,
             const float* __restrict__ b2,  const float* __restrict__ bp1,
             const float* __restrict__ wp2, int nn) {
    extern __shared__ unsigned char sm[];
    uint32_t* Xhi = (uint32_t*)(sm + SM_XHI);   // also the z-bf16 tile
    uint32_t* Xlo = (uint32_t*)(sm + SM_XLO);
    float* sbias = (float*)(sm + SM_BIAS);
    float* sbp1  = (float*)(sm + SM_BP1);
    float* swp2  = (float*)(sm + SM_WP2);

    const int t = threadIdx.x;
    const int lid = t & 31, w = t >> 5;
    const int g4 = lid >> 2, tid = lid & 3;
    const int m0 = w * 32;
    const int node0 = blockIdx.x * TILE;

    if (t < 64) { sbias[t] = bid[t]; sbias[64 + t] = b1[t]; sbias[128 + t] = b2[t]; }
    if (t < 128) { sbp1[t] = bp1[t]; swp2[t] = wp2[t]; }
    __syncthreads();

    float pw[3];

    for (int p = 0; p < 3; p++) {
        // ---- X fill: thread t -> row t (FULL 64 floats -> hi/lo bf16) -----
        {
            int node = node0 + t;
            bool valid = node < nn;
            const float* srcp = h;
            float inv = 1.f;
            if (valid) {
                if (p == 0) {
                    srcp = h + (size_t)node * 64;
                } else {
                    const float* agg = (p == 1) ? g_agg1 : g_agg2;
                    float cv = ((p == 1) ? g_cnt1 : g_cnt2)[node];
                    inv = (cv > 0.f) ? 1.f / cv : 0.f;
                    srcp = agg + (size_t)node * 64;
                }
            }
            const float4* s4 = (const float4*)srcp;
#pragma unroll
            for (int q = 0; q < 8; q++) {
                float4 a0, a1;
                if (valid) { a0 = s4[2 * q]; a1 = s4[2 * q + 1]; }
                else { a0 = make_float4(0.f,0.f,0.f,0.f); a1 = a0; }
                float x[8] = { a0.x*inv, a0.y*inv, a0.z*inv, a0.w*inv,
                               a1.x*inv, a1.y*inv, a1.z*inv, a1.w*inv };
                float l[8];
                uint32_t hu[4], lu[4];
#pragma unroll
                for (int i = 0; i < 4; i++)
                    hu[i] = pkhi(x[2*i], x[2*i+1], l[2*i], l[2*i+1]);
#pragma unroll
                for (int i = 0; i < 4; i++) lu[i] = pk2(l[2*i], l[2*i+1]);
                *(uint4*)&Xhi[t * 36 + 4 * q] = make_uint4(hu[0], hu[1], hu[2], hu[3]);
                *(uint4*)&Xlo[t * 36 + 4 * q] = make_uint4(lu[0], lu[1], lu[2], lu[3]);
            }
        }
        __syncwarp();

        // ---- GEMM1: acc[2][8][4] = X @ W^T (split bf16, 3 passes) ---------
        float acc[2][8][4];
#pragma unroll
        for (int mt = 0; mt < 2; mt++)
#pragma unroll
            for (int nt = 0; nt < 8; nt++)
#pragma unroll
                for (int i = 0; i < 4; i++) acc[mt][nt][i] = 0.f;

        const uint2* B1hp = g_B1h + (p * 4) * 256;
        const uint2* B1lp = g_B1l + (p * 4) * 256;
#pragma unroll
        for (int ks = 0; ks < 4; ks++) {
            int kw = ks * 8;
            uint32_t ah[2][4], al[2][4];
#pragma unroll
            for (int mt = 0; mt < 2; mt++) {
                int base = (m0 + mt * 16 + g4) * 36 + kw + tid;
                ah[mt][0] = Xhi[base];       ah[mt][1] = Xhi[base + 288];
                ah[mt][2] = Xhi[base + 4];   ah[mt][3] = Xhi[base + 292];
                al[mt][0] = Xlo[base];       al[mt][1] = Xlo[base + 288];
                al[mt][2] = Xlo[base + 4];   al[mt][3] = Xlo[base + 292];
            }
#pragma unroll
            for (int nt = 0; nt < 8; nt++) {
                uint2 bh = __ldg(&B1hp[(ks * 8 + nt) * 32 + lid]);
                uint2 bl = __ldg(&B1lp[(ks * 8 + nt) * 32 + lid]);
#pragma unroll
                for (int mt = 0; mt < 2; mt++) {
                    mma16816(acc[mt][nt], ah[mt], bh);
                    mma16816(acc[mt][nt], ah[mt], bl);
                    mma16816(acc[mt][nt], al[mt], bh);
                }
            }
        }
        __syncwarp();   // GEMM1 reads of Xhi done before epilogue overwrites

        // ---- epilogue1: bias/ELU, STG z fp32, STS z bf16 (into Xhi) -------
#pragma unroll
        for (int mt = 0; mt < 2; mt++) {
            int r = m0 + mt * 16 + g4;
            int nodeA = node0 + r, nodeB = nodeA + 8;
            bool vA = nodeA < nn, vB = nodeB < nn;
            float2* zA = (float2*)(g_z + ((size_t)p * nn + nodeA) * 64);
            float2* zB = (float2*)(g_z + ((size_t)p * nn + nodeB) * 64);
#pragma unroll
            for (int nt = 0; nt < 8; nt++) {
                int c = nt * 8 + tid * 2;
                float2 bb = *(float2*)&sbias[p * 64 + c];
                float v0 = acc[mt][nt][0] + bb.x;
                float v1 = acc[mt][nt][1] + bb.y;
                float v2 = acc[mt][nt][2] + bb.x;
                float v3 = acc[mt][nt][3] + bb.y;
                if (p > 0) {
                    v0 = elu(v0); v1 = elu(v1); v2 = elu(v2); v3 = elu(v3);
                }
                if (vA) zA[nt * 4 + tid] = make_float2(v0, v1);
                if (vB) zB[nt * 4 + tid] = make_float2(v2, v3);
                Xhi[r * 36 + nt * 4 + tid]       = pk2(v0, v1);
                Xhi[(r + 8) * 36 + nt * 4 + tid] = pk2(v2, v3);
            }
        }
        __syncwarp();

        // ---- GEMM2 (bf16): S = z @ Wp1^T, two n-halves; reduce tanh*wp2 ---
        float pacc = 0.f;
#pragma unroll
        for (int hh = 0; hh < 2; hh++) {
            float a2c[2][8][4];
#pragma unroll
            for (int mt = 0; mt < 2; mt++)
#pragma unroll
                for (int nt = 0; nt < 8; nt++)
#pragma unroll
                    for (int i = 0; i < 4; i++) a2c[mt][nt][i] = 0.f;
            const uint2* B3p = g_B3 + (hh * 4) * 256;
#pragma unroll
            for (int ks = 0; ks < 4; ks++) {
                int kw = ks * 8;
                uint32_t a2[2][4];
#pragma unroll
                for (int mt = 0; mt < 2; mt++) {
                    int base = (m0 + mt * 16 + g4) * 36 + kw + tid;
                    a2[mt][0] = Xhi[base];     a2[mt][1] = Xhi[base + 288];
                    a2[mt][2] = Xhi[base + 4]; a2[mt][3] = Xhi[base + 292];
                }
#pragma unroll
                for (int nt = 0; nt < 8; nt++) {
                    uint2 b = __ldg(&B3p[(ks * 8 + nt) * 32 + lid]);
#pragma unroll
                    for (int mt = 0; mt < 2; mt++) mma16816(a2c[mt][nt], a2[mt], b);
                }
            }
#pragma unroll
            for (int mt = 0; mt < 2; mt++) {
                int r = m0 + mt * 16 + g4;
                bool vA = (node0 + r) < nn, vB = (node0 + r + 8) < nn;
#pragma unroll
                for (int nt = 0; nt < 8; nt++) {
                    int c = hh * 64 + nt * 8 + tid * 2;
                    float2 bb = *(float2*)&sbp1[c];
                    float2 ww = *(float2*)&swp2[c];
                    if (vA) pacc += tanha(a2c[mt][nt][0] + bb.x) * ww.x
                                  + tanha(a2c[mt][nt][1] + bb.y) * ww.y;
                    if (vB) pacc += tanha(a2c[mt][nt][2] + bb.x) * ww.x
                                  + tanha(a2c[mt][nt][3] + bb.y) * ww.y;
                }
            }
        }
        pw[p] = pacc;
        __syncwarp();   // GEMM2 reads of Xhi done before next plane's fill
    }

    // ---- warp-reduce pw, one atomic per warp per plane ---------------------
#pragma unroll
    for (int p = 0; p < 3; p++) {
        float v = pw[p];
#pragma unroll
        for (int o = 16; o; o >>= 1) v += __shfl_xor_sync(0xffffffffu, v, o);
        if (lid == 0) atomicAdd(&g_wpart[p], v);
    }
}

// ---------------------------------------------------------------------------
__global__ void k_out(float* __restrict__ out, int n) {
    int t = blockIdx.x * blockDim.x + threadIdx.x;
    int tot = n * 16;
    if (t >= tot) return;
    float fn = (float)n;
    float w0 = g_wpart[0] / fn, w1 = g_wpart[1] / fn, w2 = g_wpart[2] / fn;
    float m = fmaxf(w0, fmaxf(w1, w2));
    float e0 = expf(w0 - m), e1 = expf(w1 - m), e2 = expf(w2 - m);
    float inv = 1.f / (e0 + e1 + e2);
    float b0 = e0 * inv, b1 = e1 * inv, b2 = e2 * inv;
    const float4* z = (const float4*)g_z;
    size_t pl = (size_t)n * 16;
    float4 a = z[t], b = z[pl + t], c = z[2 * pl + t];
    float4 o;
    o.x = b0 * a.x + b1 * b.x + b2 * c.x;
    o.y = b0 * a.y + b1 * b.y + b2 * c.y;
    o.z = b0 * a.z + b1 * b.z + b2 * c.z;
    o.w = b0 * a.w + b1 * b.w + b2 * c.w;
    ((float4*)out)[t] = o;
}

// ---------------------------------------------------------------------------
extern "C" void kernel_launch(void* const* d_in, const int* in_sizes, int n_in,
                              void* d_out, int out_size) {
    const float* h   = (const float*)d_in[0];
    const int*   s1  = (const int*)d_in[1];
    const int*   d1  = (const int*)d_in[2];
    const int*   s2  = (const int*)d_in[3];
    const int*   d2  = (const int*)d_in[4];
    const float* Wid = (const float*)d_in[5];
    const float* bid = (const float*)d_in[6];
    const float* W1  = (const float*)d_in[7];
    const float* b1  = (const float*)d_in[8];
    const float* W2  = (const float*)d_in[9];
    const float* b2  = (const float*)d_in[10];
    const float* Wp1 = (const float*)d_in[11];
    const float* bp1 = (const float*)d_in[12];
    const float* Wp2 = (const float*)d_in[13];

    int n = in_sizes[0] / D;   // 200000
    int E = in_sizes[1];       // 1000000

    cudaFuncSetAttribute(k_passA, cudaFuncAttributeMaxDynamicSharedMemorySize, SMEM_TOTAL);

    k_prep<<<1, 512>>>(Wid, W1, W2, Wp1);

    int tz = (n * 16 + 255) / 256;
    k_zero<<<tz, 256>>>(n);

    long long totS = (long long)2 * E * 16;
    k_scatter<<<(int)((totS + 255) / 256), 256>>>(h, s1, d1, s2, d2, E);

    k_passA<<<(n + TILE - 1) / TILE, 128, SMEM_TOTAL>>>(h, bid, b1, b2, bp1, Wp2, n);

    k_out<<<(n * 16 + 255) / 256, 256>>>((float*)d_out, n);
}